// round 1
// baseline (speedup 1.0000x reference)
#include <cuda_runtime.h>
#include <cuda_bf16.h>
#include <stdint.h>

// Problem: out[B=1024, W=201000] f32. out = zeros, then per row b:
//   out[b, h[b]] = 1, out[b, 100000 + r[b]] = 1, out[b, 101000 + t[b]] = 1
// Inputs (metadata order): z f32[1024,128] (unused), hID i32[1024], rID i32[1024], tID i32[1024].

#define ENTITIES_N 100000
#define RELATIONS_N 1000
#define WIDTH (2 * ENTITIES_N + RELATIONS_N)   // 201000
#define BATCH 1024

__global__ void scatter_ones_kernel(const int* __restrict__ hID,
                                    const int* __restrict__ rID,
                                    const int* __restrict__ tID,
                                    float* __restrict__ out) {
    int b = blockIdx.x * blockDim.x + threadIdx.x;
    if (b >= BATCH) return;
    long long base = (long long)b * WIDTH;
    int h = hID[b];
    int r = rID[b];
    int t = tID[b];
    out[base + h] = 1.0f;
    out[base + ENTITIES_N + r] = 1.0f;
    out[base + ENTITIES_N + RELATIONS_N + t] = 1.0f;
}

extern "C" void kernel_launch(void* const* d_in, const int* in_sizes, int n_in,
                              void* d_out, int out_size) {
    const int* hID = (const int*)d_in[1];
    const int* rID = (const int*)d_in[2];
    const int* tID = (const int*)d_in[3];
    float* out = (float*)d_out;

    // Zero the whole output (823 MB) via the HW fill path.
    cudaMemsetAsync(d_out, 0, (size_t)out_size * sizeof(float), 0);

    // Then scatter the 3072 ones.
    scatter_ones_kernel<<<(BATCH + 255) / 256, 256>>>(hID, rID, tID, out);
}

// round 2
// speedup vs baseline: 1.0039x; 1.0039x over previous
#include <cuda_runtime.h>
#include <cuda_bf16.h>
#include <stdint.h>

// out[B=1024, W=201000] f32. Fused zero-fill + one-hot scatter:
// out[b, h[b]] = 1, out[b, 100000 + r[b]] = 1, out[b, 101000 + t[b]] = 1, else 0.
// Inputs (metadata order): z f32[1024,128] (unused), hID i32[1024], rID i32[1024], tID i32[1024].

#define ENTITIES_N 100000
#define RELATIONS_N 1000
#define WIDTH (2 * ENTITIES_N + RELATIONS_N)   // 201000
#define W4 (WIDTH / 4)                         // 50250 float4 per row (exact)
#define BATCH 1024
#define F4_PER_THREAD 4
#define THREADS 256
// total float4 = 1024 * 50250 = 51,456,000 = 50250 blocks * 256 * 4 (exact)
#define NBLOCKS (BATCH * W4 / (THREADS * F4_PER_THREAD))

__global__ void __launch_bounds__(THREADS) fused_onehot_fill(
    const int* __restrict__ hID,
    const int* __restrict__ rID,
    const int* __restrict__ tID,
    float4* __restrict__ out)
{
    // Flat float4 index space; each block owns 1024 consecutive float4.
    long long base = (long long)blockIdx.x * (THREADS * F4_PER_THREAD) + threadIdx.x;

#pragma unroll
    for (int k = 0; k < F4_PER_THREAD; k++) {
        long long f4idx = base + (long long)k * THREADS;
        int row  = (int)(f4idx / W4);
        int col4 = (int)(f4idx - (long long)row * W4);
        int col  = col4 * 4;

        // Per-row hot columns (L1-broadcast loads; same addr across ~50k threads).
        int p0 = __ldg(&hID[row]);
        int p1 = ENTITIES_N + __ldg(&rID[row]);
        int p2 = ENTITIES_N + RELATIONS_N + __ldg(&tID[row]);

        float4 v;
        v.x = (col     == p0 || col     == p1 || col     == p2) ? 1.0f : 0.0f;
        v.y = (col + 1 == p0 || col + 1 == p1 || col + 1 == p2) ? 1.0f : 0.0f;
        v.z = (col + 2 == p0 || col + 2 == p1 || col + 2 == p2) ? 1.0f : 0.0f;
        v.w = (col + 3 == p0 || col + 3 == p1 || col + 3 == p2) ? 1.0f : 0.0f;

        out[f4idx] = v;
    }
}

extern "C" void kernel_launch(void* const* d_in, const int* in_sizes, int n_in,
                              void* d_out, int out_size) {
    const int* hID = (const int*)d_in[1];
    const int* rID = (const int*)d_in[2];
    const int* tID = (const int*)d_in[3];
    fused_onehot_fill<<<NBLOCKS, THREADS>>>(hID, rID, tID, (float4*)d_out);
}

// round 3
// speedup vs baseline: 1.0233x; 1.0193x over previous
#include <cuda_runtime.h>
#include <cuda_bf16.h>
#include <stdint.h>

// out[B=1024, W=201000] f32 one-hot triple scatter over zeros.
// Inputs: z f32 (unused), hID i32[1024], rID i32[1024], tID i32[1024].

#define ENTITIES_N  100000
#define RELATIONS_N 1000
#define WIDTH       201000          // 2E + R
#define W4          50250           // float4 per row (exact: 201000/4)
#define BATCH       1024
#define THREADS     256
#define F4_PER_THR  8
#define F4_PER_BLK  (THREADS * F4_PER_THR)          // 2048
#define NBLOCKS     (BATCH * W4 / F4_PER_BLK)       // 25125 (exact)

__global__ void __launch_bounds__(THREADS) fused_onehot_fill(
    const int* __restrict__ hID,
    const int* __restrict__ rID,
    const int* __restrict__ tID,
    float4* out)
{
    // Thread's first float4 index; its 8 chunks are base + k*256 (coalesced).
    const unsigned base = blockIdx.x * (unsigned)F4_PER_BLK + threadIdx.x;

    // ---- Pure fill: 8 x STG.128 of zeros, immediate offsets, no compares ----
    const float4 z = make_float4(0.f, 0.f, 0.f, 0.f);
    float4* p = out + base;
#pragma unroll
    for (int k = 0; k < F4_PER_THR; k++)
        p[k * THREADS] = z;

    // ---- Once-per-thread epilogue: overwrite owned hot elements with 1.0 ----
    // 32-bit math throughout (max flat f4 idx 51,455,999 < 2^31).
    const unsigned rowA = base / (unsigned)W4;
    const unsigned rowB = (base + (F4_PER_THR - 1) * THREADS) / (unsigned)W4;
    float* outf = (float*)out;

#pragma unroll
    for (int which = 0; which < 2; which++) {
        const unsigned row = which ? rowB : rowA;
        if (which && rowB == rowA) break;

        const unsigned rbase = row * (unsigned)WIDTH;
        unsigned q[3];
        q[0] = (unsigned)__ldg(&hID[row]);
        q[1] = (unsigned)(ENTITIES_N + __ldg(&rID[row]));
        q[2] = (unsigned)(ENTITIES_N + RELATIONS_N + __ldg(&tID[row]));

#pragma unroll
        for (int j = 0; j < 3; j++) {
            const unsigned elem  = rbase + q[j];
            const unsigned chunk = elem >> 2;
            const unsigned d     = chunk - base;   // unsigned wrap handles chunk<base
            if (d < (unsigned)F4_PER_BLK && (d & (THREADS - 1)) == 0u) {
                // This thread wrote zeros to this chunk above; same-thread
                // program order makes this 1.0 land last.
                outf[elem] = 1.0f;
            }
        }
    }
}

extern "C" void kernel_launch(void* const* d_in, const int* in_sizes, int n_in,
                              void* d_out, int out_size) {
    const int* hID = (const int*)d_in[1];
    const int* rID = (const int*)d_in[2];
    const int* tID = (const int*)d_in[3];
    fused_onehot_fill<<<NBLOCKS, THREADS>>>(hID, rID, tID, (float4*)d_out);
}